// round 3
// baseline (speedup 1.0000x reference)
#include <cuda_runtime.h>

// Problem constants (fixed shapes per reference: N=8192, D=1024, 128 classes)
#define NMAX 8192
#define MARGIN 1.0f
#define EPS 1e-6f

// Scratch: Gram matrix + row stats. Static __device__ arrays (no allocation).
__device__ float g_G[(size_t)NMAX * (size_t)NMAX];   // 256 MB
__device__ float g_sq[NMAX];                         // ||e_i||^2
__device__ float g_s[NMAX];                          // sum_k e_ik

// ---------------------------------------------------------------------------
// Row stats: sq[i] = sum e^2, s[i] = sum e. One block per row.
// ---------------------------------------------------------------------------
__global__ void __launch_bounds__(256) rowstats_kernel(const float* __restrict__ E,
                                                       int N, int D) {
    int i = blockIdx.x;
    const float* row = E + (size_t)i * D;
    float a = 0.0f, b = 0.0f;
    for (int k = threadIdx.x; k < D; k += blockDim.x) {
        float v = row[k];
        a = fmaf(v, v, a);
        b += v;
    }
#pragma unroll
    for (int off = 16; off > 0; off >>= 1) {
        a += __shfl_down_sync(0xffffffffu, a, off);
        b += __shfl_down_sync(0xffffffffu, b, off);
    }
    __shared__ float sa[8], sb[8];
    int w = threadIdx.x >> 5, l = threadIdx.x & 31;
    if (l == 0) { sa[w] = a; sb[w] = b; }
    __syncthreads();
    if (threadIdx.x == 0) {
        float A = 0.0f, B = 0.0f;
        int nw = blockDim.x >> 5;
        for (int x = 0; x < nw; x++) { A += sa[x]; B += sb[x]; }
        g_sq[i] = A;
        g_s[i] = B;
    }
}

// ---------------------------------------------------------------------------
// Symmetric SGEMM: G = E * E^T. Only lower-triangular tile pairs computed,
// the transpose tile is mirror-written. 128x128 block tile, 8x8 per thread,
// BK=8, 256 threads, single-stage smem with register prefetch of next K-slab.
// Requires N % 128 == 0, D % 8 == 0.
// ---------------------------------------------------------------------------
__global__ void __launch_bounds__(256) syrk_kernel(const float* __restrict__ E,
                                                   int N, int D) {
    int bi = blockIdx.y, bj = blockIdx.x;
    if (bj > bi) return;

    __shared__ float As[8][128];
    __shared__ float Bs[8][128];

    int tid = threadIdx.x;
    int lm = tid >> 1;            // 0..127 row within tile
    int lk = (tid & 1) << 2;      // 0 or 4

    const float* Ag = E + (size_t)(bi * 128 + lm) * D + lk;
    const float* Bg = E + (size_t)(bj * 128 + lm) * D + lk;

    int tx = tid & 15;            // 0..15 -> 8-col group
    int ty = tid >> 4;            // 0..15 -> 8-row group

    float acc[8][8];
#pragma unroll
    for (int m = 0; m < 8; m++)
#pragma unroll
        for (int n = 0; n < 8; n++) acc[m][n] = 0.0f;

    float4 a4 = *(const float4*)Ag;
    float4 b4 = *(const float4*)Bg;

    for (int k0 = 0; k0 < D; k0 += 8) {
        __syncthreads();
        As[lk + 0][lm] = a4.x; As[lk + 1][lm] = a4.y;
        As[lk + 2][lm] = a4.z; As[lk + 3][lm] = a4.w;
        Bs[lk + 0][lm] = b4.x; Bs[lk + 1][lm] = b4.y;
        Bs[lk + 2][lm] = b4.z; Bs[lk + 3][lm] = b4.w;
        __syncthreads();

        if (k0 + 8 < D) {                      // prefetch next K slab
            a4 = *(const float4*)(Ag + k0 + 8);
            b4 = *(const float4*)(Bg + k0 + 8);
        }

#pragma unroll
        for (int k = 0; k < 8; k++) {
            float af[8], bf[8];
            *(float4*)&af[0] = *(const float4*)&As[k][ty * 8];
            *(float4*)&af[4] = *(const float4*)&As[k][ty * 8 + 4];
            *(float4*)&bf[0] = *(const float4*)&Bs[k][tx * 8];
            *(float4*)&bf[4] = *(const float4*)&Bs[k][tx * 8 + 4];
#pragma unroll
            for (int m = 0; m < 8; m++)
#pragma unroll
                for (int n = 0; n < 8; n++)
                    acc[m][n] = fmaf(af[m], bf[n], acc[m][n]);
        }
    }

    int row0 = bi * 128 + ty * 8;
    int col0 = bj * 128 + tx * 8;
#pragma unroll
    for (int m = 0; m < 8; m++) {
        *(float4*)&g_G[(size_t)(row0 + m) * N + col0] =
            make_float4(acc[m][0], acc[m][1], acc[m][2], acc[m][3]);
        *(float4*)&g_G[(size_t)(row0 + m) * N + col0 + 4] =
            make_float4(acc[m][4], acc[m][5], acc[m][6], acc[m][7]);
    }
    if (bi != bj) {  // mirror tile
#pragma unroll
        for (int n = 0; n < 8; n++) {
            *(float4*)&g_G[(size_t)(col0 + n) * N + row0] =
                make_float4(acc[0][n], acc[1][n], acc[2][n], acc[3][n]);
            *(float4*)&g_G[(size_t)(col0 + n) * N + row0 + 4] =
                make_float4(acc[4][n], acc[5][n], acc[6][n], acc[7][n]);
        }
    }
}

// ---------------------------------------------------------------------------
// Mining + loss. One block (256 threads) per anchor row.
// ds[j] in shared: distance for negatives, -1 sentinel for same-class/self.
// Pass 1: hardest positive (argmax, first-index tie-break like jnp.argmax).
// Pass 2: semi-hard negative (closest with d_p < d < d_p+margin) else hardest
// (closest) negative. Loss term recomputes torch pairwise_distance with EPS.
// ---------------------------------------------------------------------------
__global__ void __launch_bounds__(256) mine_kernel(const int* __restrict__ target,
                                                   int N, int D,
                                                   float* __restrict__ out) {
    int i = blockIdx.x;
    __shared__ float ds[NMAX];
    __shared__ float rv[256];  __shared__ int rj[256];
    __shared__ float rv2[256]; __shared__ int rj2[256];

    int tid = threadIdx.x;
    int ti = target[i];
    float sqi = g_sq[i];
    const float* Gi = g_G + (size_t)i * N;

    // Pass 1: compute distances, stash negatives, track hardest positive.
    float bp = -1e30f; int bpj = 0x7fffffff;
    for (int j = tid; j < N; j += 256) {
        float d2 = fmaxf(sqi + g_sq[j] - 2.0f * Gi[j], 0.0f);
        float d = sqrtf(d2);
        if (target[j] == ti) {
            ds[j] = -1.0f;  // not a negative
            if (j != i) {
                if (d > bp || (d == bp && j < bpj)) { bp = d; bpj = j; }
            }
        } else {
            ds[j] = d;
        }
    }
    rv[tid] = bp; rj[tid] = bpj;
    __syncthreads();
    for (int st = 128; st > 0; st >>= 1) {
        if (tid < st) {
            float v = rv[tid + st]; int j = rj[tid + st];
            if (v > rv[tid] || (v == rv[tid] && j < rj[tid])) { rv[tid] = v; rj[tid] = j; }
        }
        __syncthreads();
    }
    float d_p = rv[0];
    int pos = rj[0];
    __syncthreads();

    // Pass 2: negatives. m1 = overall min, m2 = min among d > d_p.
    float m1 = 1e30f; int j1 = 0x7fffffff;
    float m2 = 1e30f; int j2 = 0x7fffffff;
    for (int j = tid; j < N; j += 256) {
        float d = ds[j];
        if (d >= 0.0f) {
            if (d < m1 || (d == m1 && j < j1)) { m1 = d; j1 = j; }
            if (d > d_p) {
                if (d < m2 || (d == m2 && j < j2)) { m2 = d; j2 = j; }
            }
        }
    }
    rv[tid] = m1; rj[tid] = j1; rv2[tid] = m2; rj2[tid] = j2;
    __syncthreads();
    for (int st = 128; st > 0; st >>= 1) {
        if (tid < st) {
            float v = rv[tid + st]; int j = rj[tid + st];
            if (v < rv[tid] || (v == rv[tid] && j < rj[tid])) { rv[tid] = v; rj[tid] = j; }
            v = rv2[tid + st]; j = rj2[tid + st];
            if (v < rv2[tid] || (v == rv2[tid] && j < rj2[tid])) { rv2[tid] = v; rj2[tid] = j; }
        }
        __syncthreads();
    }

    if (tid == 0) {
        if (pos == 0x7fffffff) pos = 0;  // degenerate (no positive) fallback; matches argmax-of-all--INF = 0
        int neg = (rv2[0] < d_p + MARGIN) ? rj2[0] : rj[0];
        if (neg == 0x7fffffff) neg = 0;

        float si = g_s[i];
        float epsC = (float)D * EPS * EPS;

        float d2p = sqi + g_sq[pos] - 2.0f * Gi[pos];
        float dp = sqrtf(fmaxf(d2p + 2.0f * EPS * (si - g_s[pos]) + epsC, 0.0f));
        float d2n = sqi + g_sq[neg] - 2.0f * Gi[neg];
        float dn = sqrtf(fmaxf(d2n + 2.0f * EPS * (si - g_s[neg]) + epsC, 0.0f));

        float term = fmaxf(dp - dn + MARGIN, 0.0f);
        atomicAdd(out, term / (float)N);
    }
}

__global__ void zero_kernel(float* out, int n) {
    int idx = blockIdx.x * blockDim.x + threadIdx.x;
    if (idx < n) out[idx] = 0.0f;
}

// ---------------------------------------------------------------------------
extern "C" void kernel_launch(void* const* d_in, const int* in_sizes, int n_in,
                              void* d_out, int out_size) {
    const float* E = (const float*)d_in[0];   // embeddings [N, D] fp32
    const int* target = (const int*)d_in[1];  // [N] int32
    float* out = (float*)d_out;

    int N = in_sizes[1];
    int D = in_sizes[0] / N;

    rowstats_kernel<<<N, 256>>>(E, N, D);

    dim3 grid(N / 128, N / 128);
    syrk_kernel<<<grid, 256>>>(E, N, D);

    zero_kernel<<<1, 32>>>(out, out_size);

    mine_kernel<<<N, 256>>>(target, N, D, out);
}

// round 6
// speedup vs baseline: 2.3387x; 2.3387x over previous
#include <cuda_runtime.h>
#include <cuda_bf16.h>
#include <cstdint>

// Problem constants (fixed shapes per reference: N=8192, D=1024, 128 classes)
#define NMAX 8192
#define DMAX 1024
#define MARGIN 1.0f
#define EPS 1e-6f

// Scratch (static __device__ arrays; no allocation).
__device__ float g_G[(size_t)NMAX * (size_t)NMAX];          // 256 MB Gram
__device__ float g_sq[NMAX];                                // ||e_i||^2 (fp32)
__device__ float g_s[NMAX];                                 // sum_k e_ik
__device__ __nv_bfloat16 g_Ehi[(size_t)NMAX * DMAX];        // bf16 hi part
__device__ __nv_bfloat16 g_Elo[(size_t)NMAX * DMAX];        // bf16 lo part

// ===========================================================================
// Helpers
// ===========================================================================
__device__ __forceinline__ uint32_t smem_to_u32(const void* p) {
    uint32_t a;
    asm("{ .reg .u64 t; cvta.to.shared.u64 t, %1; cvt.u32.u64 %0, t; }" : "=r"(a) : "l"(p));
    return a;
}
__device__ __forceinline__ void cp_async16(uint32_t smem_dst, const void* gsrc) {
    asm volatile("cp.async.cg.shared.global [%0], [%1], 16;\n" :: "r"(smem_dst), "l"(gsrc));
}
#define CP_ASYNC_COMMIT() asm volatile("cp.async.commit_group;\n" ::: "memory")
#define CP_ASYNC_WAIT1()  asm volatile("cp.async.wait_group 1;\n" ::: "memory")

__device__ __forceinline__ void ldmatrix_x4(uint32_t& r0, uint32_t& r1, uint32_t& r2, uint32_t& r3,
                                            uint32_t addr) {
    asm volatile("ldmatrix.sync.aligned.m8n8.x4.shared.b16 {%0,%1,%2,%3}, [%4];"
                 : "=r"(r0), "=r"(r1), "=r"(r2), "=r"(r3) : "r"(addr));
}
__device__ __forceinline__ void mma_bf16(float& c0, float& c1, float& c2, float& c3,
                                         uint32_t a0, uint32_t a1, uint32_t a2, uint32_t a3,
                                         uint32_t b0, uint32_t b1) {
    asm volatile("mma.sync.aligned.m16n8k16.row.col.f32.bf16.bf16.f32 "
                 "{%0,%1,%2,%3}, {%4,%5,%6,%7}, {%8,%9}, {%0,%1,%2,%3};"
                 : "+f"(c0), "+f"(c1), "+f"(c2), "+f"(c3)
                 : "r"(a0), "r"(a1), "r"(a2), "r"(a3), "r"(b0), "r"(b1));
}

// ===========================================================================
// Split fp32 -> bf16 (hi, lo) pair.  lo = bf16(x - float(hi)).
// ===========================================================================
__global__ void __launch_bounds__(256) convert_kernel(const float* __restrict__ E, int total4) {
    int idx = blockIdx.x * blockDim.x + threadIdx.x;
    if (idx >= total4) return;
    float4 v = ((const float4*)E)[idx];
    __nv_bfloat16 h0 = __float2bfloat16(v.x), h1 = __float2bfloat16(v.y);
    __nv_bfloat16 h2 = __float2bfloat16(v.z), h3 = __float2bfloat16(v.w);
    __nv_bfloat16 l0 = __float2bfloat16(v.x - __bfloat162float(h0));
    __nv_bfloat16 l1 = __float2bfloat16(v.y - __bfloat162float(h1));
    __nv_bfloat16 l2 = __float2bfloat16(v.z - __bfloat162float(h2));
    __nv_bfloat16 l3 = __float2bfloat16(v.w - __bfloat162float(h3));
    ushort4 hv, lv;
    hv.x = __bfloat16_as_ushort(h0); hv.y = __bfloat16_as_ushort(h1);
    hv.z = __bfloat16_as_ushort(h2); hv.w = __bfloat16_as_ushort(h3);
    lv.x = __bfloat16_as_ushort(l0); lv.y = __bfloat16_as_ushort(l1);
    lv.z = __bfloat16_as_ushort(l2); lv.w = __bfloat16_as_ushort(l3);
    ((ushort4*)g_Ehi)[idx] = hv;
    ((ushort4*)g_Elo)[idx] = lv;
}

// ===========================================================================
// Row stats: sq[i] = sum e^2, s[i] = sum e (fp32 exact path). One block/row.
// ===========================================================================
__global__ void __launch_bounds__(256) rowstats_kernel(const float* __restrict__ E,
                                                       int N, int D) {
    int i = blockIdx.x;
    const float* row = E + (size_t)i * D;
    float a = 0.0f, b = 0.0f;
    for (int k = threadIdx.x; k < D; k += blockDim.x) {
        float v = row[k];
        a = fmaf(v, v, a);
        b += v;
    }
#pragma unroll
    for (int off = 16; off > 0; off >>= 1) {
        a += __shfl_down_sync(0xffffffffu, a, off);
        b += __shfl_down_sync(0xffffffffu, b, off);
    }
    __shared__ float sa[8], sb[8];
    int w = threadIdx.x >> 5, l = threadIdx.x & 31;
    if (l == 0) { sa[w] = a; sb[w] = b; }
    __syncthreads();
    if (threadIdx.x == 0) {
        float A = 0.0f, B = 0.0f;
        int nw = blockDim.x >> 5;
        for (int x = 0; x < nw; x++) { A += sa[x]; B += sb[x]; }
        g_sq[i] = A;
        g_s[i] = B;
    }
}

// ===========================================================================
// Gram GEMM via mma.sync bf16 (HMMA): G = E*E^T with split-bf16 3-pass
// accumulation (hi*hi + lo*hi + hi*lo), fp32 accumulators.
// CTA tile 128x128, 8 warps (warp tile 32x64), BK=64, 3-stage cp.async.
// Symmetric: only bj<=bi tile pairs computed; mirror tile scatter-written.
// SW128 swizzle within each tile row (128B rows): for col byte c (0..127) and
// row r: swizzled = r*128 + (c ^ ((r&7)<<4)).
// ===========================================================================
#define GSTAGES 3
#define A_BYTES (128 * 128)              /* 16 KB */
#define B_BYTES (128 * 128)              /* 16 KB */
#define STAGE_BYTES (A_BYTES + B_BYTES)  /* 32 KB */
#define GRAM_SMEM (GSTAGES * STAGE_BYTES + 1024)

__global__ void __launch_bounds__(256) gram_mma_kernel(int N, int D) {
    int bi = blockIdx.y, bj = blockIdx.x;
    if (bj > bi) return;

    extern __shared__ char dsmem[];
    uint32_t base = (smem_to_u32(dsmem) + 1023u) & ~1023u;

    const int tid = threadIdx.x;
    const int wid = tid >> 5, lane = tid & 31;
    const int wm = wid & 3;       // warp row (4 x 32 = 128 M)
    const int wn = wid >> 2;      // warp col (2 x 64 = 128 N)

    const int KC = D / 64;        // k-chunks per pass (16)
    const int NC = 3 * KC;        // total chunks (48)
    const size_t rowstride = (size_t)D * 2;  // bytes per bf16 row

    // ---- loader: chunk c -> stage c%GSTAGES. 256 threads, 8 cp.async each.
    const int l_kk = tid & 7;     // 16B segment within 128B row
    const int l_r0 = tid >> 3;    // rows l_r0 + 32*i
    auto load_chunk = [&](int c) {
        int pass = c / KC;
        int kc = c - pass * KC;
        const char* Asrc = (const char*)((pass == 1) ? g_Elo : g_Ehi);
        const char* Bsrc = (const char*)((pass == 2) ? g_Elo : g_Ehi);
        uint32_t sb = base + (uint32_t)(c % GSTAGES) * STAGE_BYTES;
        const char* ga = Asrc + (size_t)(bi * 128) * rowstride + (size_t)kc * 128 + l_kk * 16;
        const char* gb = Bsrc + (size_t)(bj * 128) * rowstride + (size_t)kc * 128 + l_kk * 16;
#pragma unroll
        for (int i = 0; i < 4; i++) {
            int r = l_r0 + i * 32;
            uint32_t sw = (uint32_t)(r * 128) + (uint32_t)((l_kk * 16) ^ ((r & 7) << 4));
            cp_async16(sb + sw, ga + (size_t)r * rowstride);
            cp_async16(sb + A_BYTES + sw, gb + (size_t)r * rowstride);
        }
        CP_ASYNC_COMMIT();
    };

    // ---- per-thread ldmatrix address components (within-tile, pre-swizzle)
    // A fragments: m16 tiles at rows wm*32 + mt*16; lane -> r = row0 + (lane&15),
    // col byte = k0*2 + (lane>>4)*16.
    uint32_t a_row[2], a_xor[2];
#pragma unroll
    for (int mt = 0; mt < 2; mt++) {
        int r = wm * 32 + mt * 16 + (lane & 15);
        a_row[mt] = (uint32_t)(r * 128);
        a_xor[mt] = (uint32_t)((r & 7) << 4);
    }
    const uint32_t a_cb = (uint32_t)((lane >> 4) * 16);

    // B fragments: n16 groups at rows wn*64 + g*16;
    // lane -> r = n0 + (lane&7) + ((lane>>4)&1)*8, col byte = k0*2 + ((lane>>3)&1)*16.
    uint32_t b_row[4], b_xor[4];
#pragma unroll
    for (int g = 0; g < 4; g++) {
        int r = wn * 64 + g * 16 + (lane & 7) + ((lane >> 4) & 1) * 8;
        b_row[g] = (uint32_t)(r * 128);
        b_xor[g] = (uint32_t)((r & 7) << 4);
    }
    const uint32_t b_cb = (uint32_t)(((lane >> 3) & 1) * 16);

    float acc[2][8][4];
#pragma unroll
    for (int mt = 0; mt < 2; mt++)
#pragma unroll
        for (int nt = 0; nt < 8; nt++)
#pragma unroll
            for (int x = 0; x < 4; x++) acc[mt][nt][x] = 0.0f;

    // prologue: 2 chunks in flight
    load_chunk(0);
    load_chunk(1);

    for (int c = 0; c < NC; c++) {
        CP_ASYNC_WAIT1();
        __syncthreads();
        if (c + 2 < NC) load_chunk(c + 2);

        uint32_t sA = base + (uint32_t)(c % GSTAGES) * STAGE_BYTES;
        uint32_t sB = sA + A_BYTES;

#pragma unroll
        for (int ks = 0; ks < 4; ks++) {
            uint32_t kb = (uint32_t)(ks * 32);   // k0*2 bytes
            uint32_t af[2][4];
#pragma unroll
            for (int mt = 0; mt < 2; mt++) {
                uint32_t addr = sA + a_row[mt] + ((kb + a_cb) ^ a_xor[mt]);
                ldmatrix_x4(af[mt][0], af[mt][1], af[mt][2], af[mt][3], addr);
            }
            uint32_t bf[4][4];
#pragma unroll
            for (int g = 0; g < 4; g++) {
                uint32_t addr = sB + b_row[g] + ((kb + b_cb) ^ b_xor[g]);
                ldmatrix_x4(bf[g][0], bf[g][1], bf[g][2], bf[g][3], addr);
            }
#pragma unroll
            for (int mt = 0; mt < 2; mt++)
#pragma unroll
                for (int g = 0; g < 4; g++) {
                    mma_bf16(acc[mt][g * 2][0], acc[mt][g * 2][1], acc[mt][g * 2][2], acc[mt][g * 2][3],
                             af[mt][0], af[mt][1], af[mt][2], af[mt][3], bf[g][0], bf[g][1]);
                    mma_bf16(acc[mt][g * 2 + 1][0], acc[mt][g * 2 + 1][1], acc[mt][g * 2 + 1][2], acc[mt][g * 2 + 1][3],
                             af[mt][0], af[mt][1], af[mt][2], af[mt][3], bf[g][2], bf[g][3]);
                }
        }
    }

    // ---- epilogue: direct stores + mirror scatter (bi != bj)
    const int qr = lane >> 2;          // 0..7
    const int qc = (lane & 3) * 2;     // 0,2,4,6
#pragma unroll
    for (int mt = 0; mt < 2; mt++) {
        int gr0 = bi * 128 + wm * 32 + mt * 16 + qr;
#pragma unroll
        for (int nt = 0; nt < 8; nt++) {
            int gc = bj * 128 + wn * 64 + nt * 8 + qc;
            float* p0 = g_G + (size_t)gr0 * N + gc;
            float* p1 = g_G + (size_t)(gr0 + 8) * N + gc;
            *(float2*)p0 = make_float2(acc[mt][nt][0], acc[mt][nt][1]);
            *(float2*)p1 = make_float2(acc[mt][nt][2], acc[mt][nt][3]);
            if (bi != bj) {
                g_G[(size_t)gc * N + gr0]           = acc[mt][nt][0];
                g_G[(size_t)(gc + 1) * N + gr0]     = acc[mt][nt][1];
                g_G[(size_t)gc * N + gr0 + 8]       = acc[mt][nt][2];
                g_G[(size_t)(gc + 1) * N + gr0 + 8] = acc[mt][nt][3];
            }
        }
    }
}

// ===========================================================================
// Mining + loss (unchanged from passing R3 kernel).
// ===========================================================================
__global__ void __launch_bounds__(256) mine_kernel(const int* __restrict__ target,
                                                   int N, int D,
                                                   float* __restrict__ out) {
    int i = blockIdx.x;
    __shared__ float ds[NMAX];
    __shared__ float rv[256];  __shared__ int rj[256];
    __shared__ float rv2[256]; __shared__ int rj2[256];

    int tid = threadIdx.x;
    int ti = target[i];
    float sqi = g_sq[i];
    const float* Gi = g_G + (size_t)i * N;

    float bp = -1e30f; int bpj = 0x7fffffff;
    for (int j = tid; j < N; j += 256) {
        float d2 = fmaxf(sqi + g_sq[j] - 2.0f * Gi[j], 0.0f);
        float d = sqrtf(d2);
        if (target[j] == ti) {
            ds[j] = -1.0f;
            if (j != i) {
                if (d > bp || (d == bp && j < bpj)) { bp = d; bpj = j; }
            }
        } else {
            ds[j] = d;
        }
    }
    rv[tid] = bp; rj[tid] = bpj;
    __syncthreads();
    for (int st = 128; st > 0; st >>= 1) {
        if (tid < st) {
            float v = rv[tid + st]; int j = rj[tid + st];
            if (v > rv[tid] || (v == rv[tid] && j < rj[tid])) { rv[tid] = v; rj[tid] = j; }
        }
        __syncthreads();
    }
    float d_p = rv[0];
    int pos = rj[0];
    __syncthreads();

    float m1 = 1e30f; int j1 = 0x7fffffff;
    float m2 = 1e30f; int j2 = 0x7fffffff;
    for (int j = tid; j < N; j += 256) {
        float d = ds[j];
        if (d >= 0.0f) {
            if (d < m1 || (d == m1 && j < j1)) { m1 = d; j1 = j; }
            if (d > d_p) {
                if (d < m2 || (d == m2 && j < j2)) { m2 = d; j2 = j; }
            }
        }
    }
    rv[tid] = m1; rj[tid] = j1; rv2[tid] = m2; rj2[tid] = j2;
    __syncthreads();
    for (int st = 128; st > 0; st >>= 1) {
        if (tid < st) {
            float v = rv[tid + st]; int j = rj[tid + st];
            if (v < rv[tid] || (v == rv[tid] && j < rj[tid])) { rv[tid] = v; rj[tid] = j; }
            v = rv2[tid + st]; j = rj2[tid + st];
            if (v < rv2[tid] || (v == rv2[tid] && j < rj2[tid])) { rv2[tid] = v; rj2[tid] = j; }
        }
        __syncthreads();
    }

    if (tid == 0) {
        if (pos == 0x7fffffff) pos = 0;
        int neg = (rv2[0] < d_p + MARGIN) ? rj2[0] : rj[0];
        if (neg == 0x7fffffff) neg = 0;

        float si = g_s[i];
        float epsC = (float)D * EPS * EPS;

        float d2p = sqi + g_sq[pos] - 2.0f * Gi[pos];
        float dp = sqrtf(fmaxf(d2p + 2.0f * EPS * (si - g_s[pos]) + epsC, 0.0f));
        float d2n = sqi + g_sq[neg] - 2.0f * Gi[neg];
        float dn = sqrtf(fmaxf(d2n + 2.0f * EPS * (si - g_s[neg]) + epsC, 0.0f));

        float term = fmaxf(dp - dn + MARGIN, 0.0f);
        atomicAdd(out, term / (float)N);
    }
}

__global__ void zero_kernel(float* out, int n) {
    int idx = blockIdx.x * blockDim.x + threadIdx.x;
    if (idx < n) out[idx] = 0.0f;
}

// ---------------------------------------------------------------------------
extern "C" void kernel_launch(void* const* d_in, const int* in_sizes, int n_in,
                              void* d_out, int out_size) {
    const float* E = (const float*)d_in[0];   // embeddings [N, D] fp32
    const int* target = (const int*)d_in[1];  // [N] int32
    float* out = (float*)d_out;

    int N = in_sizes[1];
    int D = in_sizes[0] / N;

    convert_kernel<<<(N * D / 4 + 255) / 256, 256>>>(E, N * D / 4);
    rowstats_kernel<<<N, 256>>>(E, N, D);

    cudaFuncSetAttribute(gram_mma_kernel, cudaFuncAttributeMaxDynamicSharedMemorySize, GRAM_SMEM);
    dim3 grid(N / 128, N / 128);
    gram_mma_kernel<<<grid, 256, GRAM_SMEM>>>(N, D);

    zero_kernel<<<1, 32>>>(out, out_size);

    mine_kernel<<<N, 256>>>(target, N, D, out);
}

// round 7
// speedup vs baseline: 2.8353x; 1.2123x over previous
#include <cuda_runtime.h>
#include <cuda_bf16.h>
#include <cstdint>

// Problem constants (fixed shapes per reference: N=8192, D=1024, 128 classes)
#define NMAX 8192
#define DMAX 1024
#define MARGIN 1.0f
#define EPS 1e-6f

// Scratch (static __device__ arrays; no allocation).
__device__ float g_G[(size_t)NMAX * (size_t)NMAX];          // 256 MB Gram
__device__ float g_sq[NMAX];                                // ||e_i||^2 (fp32)
__device__ float g_s[NMAX];                                 // sum_k e_ik
__device__ __nv_bfloat16 g_Ehi[(size_t)NMAX * DMAX];        // bf16 hi part
__device__ __nv_bfloat16 g_Elo[(size_t)NMAX * DMAX];        // bf16 lo part

// ===========================================================================
// Helpers
// ===========================================================================
__device__ __forceinline__ uint32_t smem_to_u32(const void* p) {
    uint32_t a;
    asm("{ .reg .u64 t; cvta.to.shared.u64 t, %1; cvt.u32.u64 %0, t; }" : "=r"(a) : "l"(p));
    return a;
}
__device__ __forceinline__ void cp_async16(uint32_t smem_dst, const void* gsrc) {
    asm volatile("cp.async.cg.shared.global [%0], [%1], 16;\n" :: "r"(smem_dst), "l"(gsrc));
}
#define CP_ASYNC_COMMIT() asm volatile("cp.async.commit_group;\n" ::: "memory")
#define CP_ASYNC_WAIT1()  asm volatile("cp.async.wait_group 1;\n" ::: "memory")

__device__ __forceinline__ void ldmatrix_x4(uint32_t& r0, uint32_t& r1, uint32_t& r2, uint32_t& r3,
                                            uint32_t addr) {
    asm volatile("ldmatrix.sync.aligned.m8n8.x4.shared.b16 {%0,%1,%2,%3}, [%4];"
                 : "=r"(r0), "=r"(r1), "=r"(r2), "=r"(r3) : "r"(addr));
}
__device__ __forceinline__ void mma_bf16(float& c0, float& c1, float& c2, float& c3,
                                         uint32_t a0, uint32_t a1, uint32_t a2, uint32_t a3,
                                         uint32_t b0, uint32_t b1) {
    asm volatile("mma.sync.aligned.m16n8k16.row.col.f32.bf16.bf16.f32 "
                 "{%0,%1,%2,%3}, {%4,%5,%6,%7}, {%8,%9}, {%0,%1,%2,%3};"
                 : "+f"(c0), "+f"(c1), "+f"(c2), "+f"(c3)
                 : "r"(a0), "r"(a1), "r"(a2), "r"(a3), "r"(b0), "r"(b1));
}

// ===========================================================================
// Split fp32 -> bf16 (hi, lo) pair.  lo = bf16(x - float(hi)).
// ===========================================================================
__global__ void __launch_bounds__(256) convert_kernel(const float* __restrict__ E, int total4) {
    int idx = blockIdx.x * blockDim.x + threadIdx.x;
    if (idx >= total4) return;
    float4 v = ((const float4*)E)[idx];
    __nv_bfloat16 h0 = __float2bfloat16(v.x), h1 = __float2bfloat16(v.y);
    __nv_bfloat16 h2 = __float2bfloat16(v.z), h3 = __float2bfloat16(v.w);
    __nv_bfloat16 l0 = __float2bfloat16(v.x - __bfloat162float(h0));
    __nv_bfloat16 l1 = __float2bfloat16(v.y - __bfloat162float(h1));
    __nv_bfloat16 l2 = __float2bfloat16(v.z - __bfloat162float(h2));
    __nv_bfloat16 l3 = __float2bfloat16(v.w - __bfloat162float(h3));
    ushort4 hv, lv;
    hv.x = __bfloat16_as_ushort(h0); hv.y = __bfloat16_as_ushort(h1);
    hv.z = __bfloat16_as_ushort(h2); hv.w = __bfloat16_as_ushort(h3);
    lv.x = __bfloat16_as_ushort(l0); lv.y = __bfloat16_as_ushort(l1);
    lv.z = __bfloat16_as_ushort(l2); lv.w = __bfloat16_as_ushort(l3);
    ((ushort4*)g_Ehi)[idx] = hv;
    ((ushort4*)g_Elo)[idx] = lv;
}

// ===========================================================================
// Row stats: sq[i] = sum e^2, s[i] = sum e. One block per row, float4 loads.
// Also zeroes the output scalar (block 0) so no separate zero kernel.
// ===========================================================================
__global__ void __launch_bounds__(256) rowstats_kernel(const float* __restrict__ E,
                                                       int N, int D,
                                                       float* __restrict__ out) {
    int i = blockIdx.x;
    if (i == 0 && threadIdx.x == 0) out[0] = 0.0f;
    const float4* row = (const float4*)(E + (size_t)i * D);
    float a = 0.0f, b = 0.0f;
    for (int k = threadIdx.x; k < D / 4; k += blockDim.x) {
        float4 v = row[k];
        a = fmaf(v.x, v.x, a); a = fmaf(v.y, v.y, a);
        a = fmaf(v.z, v.z, a); a = fmaf(v.w, v.w, a);
        b += v.x + v.y + v.z + v.w;
    }
#pragma unroll
    for (int off = 16; off > 0; off >>= 1) {
        a += __shfl_down_sync(0xffffffffu, a, off);
        b += __shfl_down_sync(0xffffffffu, b, off);
    }
    __shared__ float sa[8], sb[8];
    int w = threadIdx.x >> 5, l = threadIdx.x & 31;
    if (l == 0) { sa[w] = a; sb[w] = b; }
    __syncthreads();
    if (threadIdx.x == 0) {
        float A = 0.0f, B = 0.0f;
        int nw = blockDim.x >> 5;
        for (int x = 0; x < nw; x++) { A += sa[x]; B += sb[x]; }
        g_sq[i] = A;
        g_s[i] = B;
    }
}

// ===========================================================================
// Gram GEMM via mma.sync bf16 (HMMA): unchanged from the passing R6 kernel.
// ===========================================================================
#define GSTAGES 3
#define A_BYTES (128 * 128)              /* 16 KB */
#define B_BYTES (128 * 128)              /* 16 KB */
#define STAGE_BYTES (A_BYTES + B_BYTES)  /* 32 KB */
#define GRAM_SMEM (GSTAGES * STAGE_BYTES + 1024)

__global__ void __launch_bounds__(256) gram_mma_kernel(int N, int D) {
    int bi = blockIdx.y, bj = blockIdx.x;
    if (bj > bi) return;

    extern __shared__ char dsmem[];
    uint32_t base = (smem_to_u32(dsmem) + 1023u) & ~1023u;

    const int tid = threadIdx.x;
    const int wid = tid >> 5, lane = tid & 31;
    const int wm = wid & 3;       // warp row (4 x 32 = 128 M)
    const int wn = wid >> 2;      // warp col (2 x 64 = 128 N)

    const int KC = D / 64;        // k-chunks per pass (16)
    const int NC = 3 * KC;        // total chunks (48)
    const size_t rowstride = (size_t)D * 2;  // bytes per bf16 row

    const int l_kk = tid & 7;     // 16B segment within 128B row
    const int l_r0 = tid >> 3;    // rows l_r0 + 32*i
    auto load_chunk = [&](int c) {
        int pass = c / KC;
        int kc = c - pass * KC;
        const char* Asrc = (const char*)((pass == 1) ? g_Elo : g_Ehi);
        const char* Bsrc = (const char*)((pass == 2) ? g_Elo : g_Ehi);
        uint32_t sb = base + (uint32_t)(c % GSTAGES) * STAGE_BYTES;
        const char* ga = Asrc + (size_t)(bi * 128) * rowstride + (size_t)kc * 128 + l_kk * 16;
        const char* gb = Bsrc + (size_t)(bj * 128) * rowstride + (size_t)kc * 128 + l_kk * 16;
#pragma unroll
        for (int i = 0; i < 4; i++) {
            int r = l_r0 + i * 32;
            uint32_t sw = (uint32_t)(r * 128) + (uint32_t)((l_kk * 16) ^ ((r & 7) << 4));
            cp_async16(sb + sw, ga + (size_t)r * rowstride);
            cp_async16(sb + A_BYTES + sw, gb + (size_t)r * rowstride);
        }
        CP_ASYNC_COMMIT();
    };

    uint32_t a_row[2], a_xor[2];
#pragma unroll
    for (int mt = 0; mt < 2; mt++) {
        int r = wm * 32 + mt * 16 + (lane & 15);
        a_row[mt] = (uint32_t)(r * 128);
        a_xor[mt] = (uint32_t)((r & 7) << 4);
    }
    const uint32_t a_cb = (uint32_t)((lane >> 4) * 16);

    uint32_t b_row[4], b_xor[4];
#pragma unroll
    for (int g = 0; g < 4; g++) {
        int r = wn * 64 + g * 16 + (lane & 7) + ((lane >> 4) & 1) * 8;
        b_row[g] = (uint32_t)(r * 128);
        b_xor[g] = (uint32_t)((r & 7) << 4);
    }
    const uint32_t b_cb = (uint32_t)(((lane >> 3) & 1) * 16);

    float acc[2][8][4];
#pragma unroll
    for (int mt = 0; mt < 2; mt++)
#pragma unroll
        for (int nt = 0; nt < 8; nt++)
#pragma unroll
            for (int x = 0; x < 4; x++) acc[mt][nt][x] = 0.0f;

    load_chunk(0);
    load_chunk(1);

    for (int c = 0; c < NC; c++) {
        CP_ASYNC_WAIT1();
        __syncthreads();
        if (c + 2 < NC) load_chunk(c + 2);

        uint32_t sA = base + (uint32_t)(c % GSTAGES) * STAGE_BYTES;
        uint32_t sB = sA + A_BYTES;

#pragma unroll
        for (int ks = 0; ks < 4; ks++) {
            uint32_t kb = (uint32_t)(ks * 32);
            uint32_t af[2][4];
#pragma unroll
            for (int mt = 0; mt < 2; mt++) {
                uint32_t addr = sA + a_row[mt] + ((kb + a_cb) ^ a_xor[mt]);
                ldmatrix_x4(af[mt][0], af[mt][1], af[mt][2], af[mt][3], addr);
            }
            uint32_t bf[4][4];
#pragma unroll
            for (int g = 0; g < 4; g++) {
                uint32_t addr = sB + b_row[g] + ((kb + b_cb) ^ b_xor[g]);
                ldmatrix_x4(bf[g][0], bf[g][1], bf[g][2], bf[g][3], addr);
            }
#pragma unroll
            for (int mt = 0; mt < 2; mt++)
#pragma unroll
                for (int g = 0; g < 4; g++) {
                    mma_bf16(acc[mt][g * 2][0], acc[mt][g * 2][1], acc[mt][g * 2][2], acc[mt][g * 2][3],
                             af[mt][0], af[mt][1], af[mt][2], af[mt][3], bf[g][0], bf[g][1]);
                    mma_bf16(acc[mt][g * 2 + 1][0], acc[mt][g * 2 + 1][1], acc[mt][g * 2 + 1][2], acc[mt][g * 2 + 1][3],
                             af[mt][0], af[mt][1], af[mt][2], af[mt][3], bf[g][2], bf[g][3]);
                }
        }
    }

    const int qr = lane >> 2;
    const int qc = (lane & 3) * 2;
#pragma unroll
    for (int mt = 0; mt < 2; mt++) {
        int gr0 = bi * 128 + wm * 32 + mt * 16 + qr;
#pragma unroll
        for (int nt = 0; nt < 8; nt++) {
            int gc = bj * 128 + wn * 64 + nt * 8 + qc;
            float* p0 = g_G + (size_t)gr0 * N + gc;
            float* p1 = g_G + (size_t)(gr0 + 8) * N + gc;
            *(float2*)p0 = make_float2(acc[mt][nt][0], acc[mt][nt][1]);
            *(float2*)p1 = make_float2(acc[mt][nt][2], acc[mt][nt][3]);
            if (bi != bj) {
                g_G[(size_t)gc * N + gr0]           = acc[mt][nt][0];
                g_G[(size_t)(gc + 1) * N + gr0]     = acc[mt][nt][1];
                g_G[(size_t)gc * N + gr0 + 8]       = acc[mt][nt][2];
                g_G[(size_t)(gc + 1) * N + gr0 + 8] = acc[mt][nt][3];
            }
        }
    }
}

// ===========================================================================
// Mining + loss, vectorized. All selection done on squared distances (d^2):
// argmax / argmin / semi-hard window are monotonic under sqrt, so only ONE
// sqrt per row is needed (to form the (d_p + margin)^2 window bound), and the
// final dp/dn are recomputed exactly with the torch EPS correction.
// float4 loads of G row (MLP=8 per thread), float4 shared traffic.
// ===========================================================================
__global__ void __launch_bounds__(256) mine_kernel(const int* __restrict__ target,
                                                   int N, int D,
                                                   float* __restrict__ out) {
    int i = blockIdx.x;
    __shared__ float ds[NMAX];          // d^2 for negatives, -1 sentinel else
    __shared__ float rv[256];  __shared__ int rj[256];
    __shared__ float rv2[256]; __shared__ int rj2[256];

    const int tid = threadIdx.x;
    const int ti = target[i];
    const float sqi = g_sq[i];
    const float* Gi = g_G + (size_t)i * N;
    const float4* Gi4 = (const float4*)Gi;
    const float4* sq4 = (const float4*)g_sq;
    const int4*   tg4 = (const int4*)target;

    // Pass 1: d^2 for all j; stash negatives; track hardest positive (max d^2).
    float bp = -1e30f; int bpj = 0x7fffffff;
    const int NV = NMAX / 4 / 256;      // 8 iterations
#pragma unroll
    for (int v = 0; v < NV; v++) {
        int idx = tid + v * 256;        // float4 index, increasing j per thread
        float4 g = Gi4[idx];
        float4 s = sq4[idx];
        int4   t = tg4[idx];
        int j = idx * 4;
        float4 d2;
        d2.x = fmaxf(sqi + s.x - 2.0f * g.x, 0.0f);
        d2.y = fmaxf(sqi + s.y - 2.0f * g.y, 0.0f);
        d2.z = fmaxf(sqi + s.z - 2.0f * g.z, 0.0f);
        d2.w = fmaxf(sqi + s.w - 2.0f * g.w, 0.0f);
        float4 r = d2;
        if (t.x == ti) { r.x = -1.0f; if (j + 0 != i && d2.x > bp) { bp = d2.x; bpj = j + 0; } }
        if (t.y == ti) { r.y = -1.0f; if (j + 1 != i && d2.y > bp) { bp = d2.y; bpj = j + 1; } }
        if (t.z == ti) { r.z = -1.0f; if (j + 2 != i && d2.z > bp) { bp = d2.z; bpj = j + 2; } }
        if (t.w == ti) { r.w = -1.0f; if (j + 3 != i && d2.w > bp) { bp = d2.w; bpj = j + 3; } }
        ((float4*)ds)[idx] = r;
    }
    rv[tid] = bp; rj[tid] = bpj;
    __syncthreads();
    for (int st = 128; st > 0; st >>= 1) {
        if (tid < st) {
            float v = rv[tid + st]; int j = rj[tid + st];
            if (v > rv[tid] || (v == rv[tid] && j < rj[tid])) { rv[tid] = v; rj[tid] = j; }
        }
        __syncthreads();
    }
    const float dp2 = rv[0];            // hardest-positive d^2
    const int pos = rj[0];
    __syncthreads();

    // Window bound in d^2 space: (sqrt(dp2) + margin)^2. One sqrt per row.
    const float dpv = sqrtf(fmaxf(dp2, 0.0f));
    const float hi2 = (dpv + MARGIN) * (dpv + MARGIN);

    // Pass 2: negatives on d^2. m1 = overall min, m2 = min among d^2 > dp2.
    float m1 = 1e30f; int j1 = 0x7fffffff;
    float m2 = 1e30f; int j2 = 0x7fffffff;
#pragma unroll
    for (int v = 0; v < NV; v++) {
        int idx = tid + v * 256;
        float4 d = ((const float4*)ds)[idx];
        int j = idx * 4;
        if (d.x >= 0.0f) { if (d.x < m1) { m1 = d.x; j1 = j + 0; }
                           if (d.x > dp2 && d.x < m2) { m2 = d.x; j2 = j + 0; } }
        if (d.y >= 0.0f) { if (d.y < m1) { m1 = d.y; j1 = j + 1; }
                           if (d.y > dp2 && d.y < m2) { m2 = d.y; j2 = j + 1; } }
        if (d.z >= 0.0f) { if (d.z < m1) { m1 = d.z; j1 = j + 2; }
                           if (d.z > dp2 && d.z < m2) { m2 = d.z; j2 = j + 2; } }
        if (d.w >= 0.0f) { if (d.w < m1) { m1 = d.w; j1 = j + 3; }
                           if (d.w > dp2 && d.w < m2) { m2 = d.w; j2 = j + 3; } }
    }
    rv[tid] = m1; rj[tid] = j1; rv2[tid] = m2; rj2[tid] = j2;
    __syncthreads();
    for (int st = 128; st > 0; st >>= 1) {
        if (tid < st) {
            float v = rv[tid + st]; int j = rj[tid + st];
            if (v < rv[tid] || (v == rv[tid] && j < rj[tid])) { rv[tid] = v; rj[tid] = j; }
            v = rv2[tid + st]; j = rj2[tid + st];
            if (v < rv2[tid] || (v == rv2[tid] && j < rj2[tid])) { rv2[tid] = v; rj2[tid] = j; }
        }
        __syncthreads();
    }

    if (tid == 0) {
        int p = (pos == 0x7fffffff) ? 0 : pos;
        int neg = (rv2[0] < hi2) ? rj2[0] : rj[0];
        if (neg == 0x7fffffff) neg = 0;

        float si = g_s[i];
        float epsC = (float)D * EPS * EPS;

        float d2p = sqi + g_sq[p] - 2.0f * Gi[p];
        float dp = sqrtf(fmaxf(d2p + 2.0f * EPS * (si - g_s[p]) + epsC, 0.0f));
        float d2n = sqi + g_sq[neg] - 2.0f * Gi[neg];
        float dn = sqrtf(fmaxf(d2n + 2.0f * EPS * (si - g_s[neg]) + epsC, 0.0f));

        float term = fmaxf(dp - dn + MARGIN, 0.0f);
        atomicAdd(out, term / (float)N);
    }
}

// ---------------------------------------------------------------------------
extern "C" void kernel_launch(void* const* d_in, const int* in_sizes, int n_in,
                              void* d_out, int out_size) {
    const float* E = (const float*)d_in[0];   // embeddings [N, D] fp32
    const int* target = (const int*)d_in[1];  // [N] int32
    float* out = (float*)d_out;

    int N = in_sizes[1];
    int D = in_sizes[0] / N;

    convert_kernel<<<(N * D / 4 + 255) / 256, 256>>>(E, N * D / 4);
    rowstats_kernel<<<N, 256>>>(E, N, D, out);

    cudaFuncSetAttribute(gram_mma_kernel, cudaFuncAttributeMaxDynamicSharedMemorySize, GRAM_SMEM);
    dim3 grid(N / 128, N / 128);
    gram_mma_kernel<<<grid, 256, GRAM_SMEM>>>(N, D);

    mine_kernel<<<N, 256>>>(target, N, D, out);
}